// round 12
// baseline (speedup 1.0000x reference)
#include <cuda_runtime.h>
#include <cuda_fp16.h>
#include <math.h>
#include <stdint.h>

// Problem constants
#define B_SZ   256
#define IN_SZ  512
#define OUT_SZ 512
#define R_SZ   4
#define H_SZ   4608             // (IN+OUT)*R + OUT
#define G4_SZ  (4*H_SZ)         // 18432  (gate columns)
#define NX_SZ  (G4_SZ + OUT_SZ) // 18944
#define K_TOT  (IN_SZ + H_SZ)   // 5120

// GEMM tile config (fp16 mma.sync m16n8k16) — round-5 measured core
#define BM 128
#define BN 128
#define BK 32
#define BKP 40                  // padded row (80 B: 16B-aligned, conflict-free)
#define NTHREADS 256

// Scratch (no cudaMalloc allowed)
__device__ float g_xw0[B_SZ * OUT_SZ];    // x @ W0^T
__device__ float g_z[B_SZ * R_SZ];

// ---------------------------------------------------------------------------
__device__ __forceinline__ void mma_f16(float c[4],
                                        uint32_t a0, uint32_t a1, uint32_t a2, uint32_t a3,
                                        uint32_t b0, uint32_t b1) {
    asm volatile(
        "mma.sync.aligned.m16n8k16.row.col.f32.f16.f16.f32 "
        "{%0,%1,%2,%3}, {%4,%5,%6,%7}, {%8,%9}, {%0,%1,%2,%3};"
        : "+f"(c[0]), "+f"(c[1]), "+f"(c[2]), "+f"(c[3])
        : "r"(a0), "r"(a1), "r"(a2), "r"(a3), "r"(b0), "r"(b1));
}

__device__ __forceinline__ uint32_t h2u(__half2 h) {
    return *reinterpret_cast<uint32_t*>(&h);
}

__device__ __forceinline__ float sigm(float v) { return 1.0f / (1.0f + expf(-v)); }

// ---------------------------------------------------------------------------
// Kernel 1: fused gates-GEMM + LSTM elementwise.
// Gate tiles use an INTERLEAVED column layout: column n <-> gate (n&3) of
// unit (n>>2), i.e. weight row (n&3)*H + (n>>2). A 128-col tile = 32 h-units
// with all 4 gates -> epilogue computes c_new/h_new in-kernel and writes
// them coalesced via an smem transpose. W0 tiles (bn >= G4) write g_xw0.
// ---------------------------------------------------------------------------
__global__ __launch_bounds__(NTHREADS, 2)
void gates_gemm_fused(const float* __restrict__ x,  const float* __restrict__ h0,
                      const float* __restrict__ c0,
                      const float* __restrict__ Wih, const float* __restrict__ Whh,
                      const float* __restrict__ bih, const float* __restrict__ bhh,
                      const float* __restrict__ W0,
                      float* __restrict__ h_out, float* __restrict__ c_out)
{
    __shared__ __align__(16) __half As[2][BM][BKP];
    __shared__ __align__(16) __half Bs[2][BN][BKP];

    const int tid = threadIdx.x;
    const int bm  = blockIdx.y * BM;
    const int bn  = blockIdx.x * BN;
    const bool isW0 = (bn >= G4_SZ);                      // block-uniform
    const int NIT = isW0 ? (IN_SZ / BK) : (K_TOT / BK);   // 16 or 160

    const int warp = tid >> 5;
    const int lane = tid & 31;
    const int wm0 = (warp & 3) * 32;   // warp m-strip
    const int wn0 = (warp >> 2) * 64;  // warp n-strip
    const int q   = lane & 3;
    const int t8  = lane >> 2;

    float acc[2][8][4];
#pragma unroll
    for (int mi = 0; mi < 2; mi++)
#pragma unroll
        for (int ni = 0; ni < 8; ni++)
#pragma unroll
            for (int e = 0; e < 4; e++) acc[mi][ni][e] = 0.f;

    float4 ra[4], rb[4];

    auto ldg_tile = [&](int t) {
        const int k0 = t * BK;
        const float* baseA; long sA;
        if (k0 < IN_SZ) { baseA = x + (long)bm * IN_SZ + k0; sA = IN_SZ; }
        else            { baseA = h0 + (long)bm * H_SZ + (k0 - IN_SZ); sA = H_SZ; }
#pragma unroll
        for (int j = 0; j < 4; j++) {
            int ch = j * 256 + tid, row = ch >> 3, c = ch & 7;
            ra[j] = *reinterpret_cast<const float4*>(baseA + (long)row * sA + c * 4);
        }
#pragma unroll
        for (int j = 0; j < 4; j++) {
            int ch = j * 256 + tid, row = ch >> 3, c = ch & 7;
            const int n = bn + row;
            const float* p;
            if (isW0) {
                p = W0 + (long)(n - G4_SZ) * IN_SZ + k0 + c * 4;
            } else {
                // interleaved gate layout: weight row = (n&3)*H + (n>>2)
                const int wrow = (n & 3) * H_SZ + (n >> 2);
                p = (k0 < IN_SZ) ? (Wih + (long)wrow * IN_SZ + k0 + c * 4)
                                 : (Whh + (long)wrow * H_SZ + (k0 - IN_SZ) + c * 4);
            }
            rb[j] = *reinterpret_cast<const float4*>(p);
        }
    };

    auto sts_tile = [&](int buf) {
#pragma unroll
        for (int j = 0; j < 4; j++) {
            int ch = j * 256 + tid, row = ch >> 3, c = ch & 7;
            __half2 ha = __floats2half2_rn(ra[j].x, ra[j].y);
            __half2 hb = __floats2half2_rn(ra[j].z, ra[j].w);
            *reinterpret_cast<uint2*>(&As[buf][row][c * 4]) = make_uint2(h2u(ha), h2u(hb));
        }
#pragma unroll
        for (int j = 0; j < 4; j++) {
            int ch = j * 256 + tid, row = ch >> 3, c = ch & 7;
            __half2 ha = __floats2half2_rn(rb[j].x, rb[j].y);
            __half2 hb = __floats2half2_rn(rb[j].z, rb[j].w);
            *reinterpret_cast<uint2*>(&Bs[buf][row][c * 4]) = make_uint2(h2u(ha), h2u(hb));
        }
    };

    auto compute = [&](int buf) {
#pragma unroll
        for (int ks = 0; ks < 2; ks++) {
            const int kb = ks * 16;
            uint32_t a[2][4];
#pragma unroll
            for (int mi = 0; mi < 2; mi++) {
                int r0 = wm0 + mi * 16 + t8;
                a[mi][0] = h2u(*reinterpret_cast<const __half2*>(&As[buf][r0    ][kb + 2 * q    ]));
                a[mi][1] = h2u(*reinterpret_cast<const __half2*>(&As[buf][r0 + 8][kb + 2 * q    ]));
                a[mi][2] = h2u(*reinterpret_cast<const __half2*>(&As[buf][r0    ][kb + 2 * q + 8]));
                a[mi][3] = h2u(*reinterpret_cast<const __half2*>(&As[buf][r0 + 8][kb + 2 * q + 8]));
            }
#pragma unroll
            for (int ni = 0; ni < 8; ni++) {
                int nc = wn0 + ni * 8 + t8;
                uint32_t b0 = h2u(*reinterpret_cast<const __half2*>(&Bs[buf][nc][kb + 2 * q    ]));
                uint32_t b1 = h2u(*reinterpret_cast<const __half2*>(&Bs[buf][nc][kb + 2 * q + 8]));
                mma_f16(acc[0][ni], a[0][0], a[0][1], a[0][2], a[0][3], b0, b1);
                mma_f16(acc[1][ni], a[1][0], a[1][1], a[1][2], a[1][3], b0, b1);
            }
        }
    };

    // prologue
    ldg_tile(0);
    sts_tile(0);
    __syncthreads();

    int buf = 0;
    for (int t = 1; t < NIT; t++) {
        ldg_tile(t);
        compute(buf);
        sts_tile(buf ^ 1);
        __syncthreads();
        buf ^= 1;
    }
    compute(buf);

    if (isW0) {
        // x @ W0^T epilogue (no bias)
#pragma unroll
        for (int ni = 0; ni < 8; ni++) {
            const int n2 = bn + wn0 + ni * 8 + q * 2 - G4_SZ;
#pragma unroll
            for (int mi = 0; mi < 2; mi++) {
                const int row = bm + wm0 + mi * 16 + t8;
                float2 v0 = make_float2(acc[mi][ni][0], acc[mi][ni][1]);
                float2 v1 = make_float2(acc[mi][ni][2], acc[mi][ni][3]);
                *reinterpret_cast<float2*>(g_xw0 + (long)row * OUT_SZ + n2)       = v0;
                *reinterpret_cast<float2*>(g_xw0 + (long)(row + 8) * OUT_SZ + n2) = v1;
            }
        }
        return;
    }

    // ---- fused LSTM elementwise epilogue (gate tiles) ----
    __syncthreads();   // all warps done reading As/Bs before smem reuse
    float* shc = reinterpret_cast<float*>(&As[0][0][0]);   // [128][33]
    float* shh = shc + 128 * 33;                           // total 33792 B <= 40960
    const bool even = ((lane & 1) == 0);

#pragma unroll
    for (int ni = 0; ni < 8; ni++) {
        const int c = wn0 + ni * 8 + q * 2;
        const int n = bn + c;
        const int g = n & 3;              // 0 or 2 (c even)
        const int h = n >> 2;
        const float bv0 = bih[g * H_SZ + h] + bhh[g * H_SZ + h];
        const float bv1 = bih[(g + 1) * H_SZ + h] + bhh[(g + 1) * H_SZ + h];
#pragma unroll
        for (int mi = 0; mi < 2; mi++) {
            const int r  = bm + wm0 + mi * 16 + t8;   // global batch row
            const int rl = wm0 + mi * 16 + t8;        // local row
            float p0 = acc[mi][ni][0] + bv0;
            float p1 = acc[mi][ni][1] + bv1;
            float p2 = acc[mi][ni][2] + bv0;
            float p3 = acc[mi][ni][3] + bv1;
            float e0 = __shfl_xor_sync(0xffffffffu, p0, 1);
            float e1 = __shfl_xor_sync(0xffffffffu, p1, 1);
            float e2 = __shfl_xor_sync(0xffffffffu, p2, 1);
            float e3 = __shfl_xor_sync(0xffffffffu, p3, 1);
            if (even) {
                // even lane owns (i,f), partner supplies (g,o); same h.
                const int hl = h - (bn >> 2);         // 0..31
                float c0a = c0[(long)r * H_SZ + h];
                float cc = sigm(p1) * c0a + sigm(p0) * tanhf(e0);
                float hn = sigm(e1) * tanhf(cc);
                shc[rl * 33 + hl] = cc;
                shh[rl * 33 + hl] = hn;

                float c0b = c0[(long)(r + 8) * H_SZ + h];
                cc = sigm(p3) * c0b + sigm(p2) * tanhf(e2);
                hn = sigm(e3) * tanhf(cc);
                shc[(rl + 8) * 33 + hl] = cc;
                shh[(rl + 8) * 33 + hl] = hn;
            }
        }
    }
    __syncthreads();

    // coalesced writeback: 128 rows x 32 h
    const int hcol0 = bn >> 2;
#pragma unroll
    for (int j = 0; j < 4; j++) {
        int ch = j * 256 + tid;          // 0..1023 = 128 rows * 8 float4
        int rl = ch >> 3, c8 = (ch & 7) * 4;
        float4 vc, vh;
        vc.x = shc[rl * 33 + c8 + 0]; vc.y = shc[rl * 33 + c8 + 1];
        vc.z = shc[rl * 33 + c8 + 2]; vc.w = shc[rl * 33 + c8 + 3];
        vh.x = shh[rl * 33 + c8 + 0]; vh.y = shh[rl * 33 + c8 + 1];
        vh.z = shh[rl * 33 + c8 + 2]; vh.w = shh[rl * 33 + c8 + 3];
        *reinterpret_cast<float4*>(c_out + (long)(bm + rl) * H_SZ + hcol0 + c8) = vc;
        *reinterpret_cast<float4*>(h_out + (long)(bm + rl) * H_SZ + hcol0 + c8) = vh;
    }
}

// ---------------------------------------------------------------------------
// Kernel 2: z[b,r] = dot(h_new[b, 2048 + r*512 + :], x[b,:])
// ---------------------------------------------------------------------------
__global__ __launch_bounds__(128)
void z_kernel(const float* __restrict__ hn, const float* __restrict__ x)
{
    int b    = blockIdx.x;
    int r    = threadIdx.x >> 5;
    int lane = threadIdx.x & 31;
    const float* dw2 = hn + (long)b * H_SZ + OUT_SZ * R_SZ + r * IN_SZ;
    const float* xb  = x + b * IN_SZ;
    float s = 0.f;
    for (int i = lane; i < IN_SZ; i += 32) s = fmaf(dw2[i], xb[i], s);
#pragma unroll
    for (int off = 16; off; off >>= 1) s += __shfl_xor_sync(0xffffffffu, s, off);
    if (lane == 0) g_z[b * R_SZ + r] = s;
}

// ---------------------------------------------------------------------------
// Kernel 3: y[b,o] = xw0[b,o] + bias0[o] + db[b,o] + sum_r dw1[b,o,r]*z[b,r]
// ---------------------------------------------------------------------------
__global__ __launch_bounds__(256)
void y_final(const float* __restrict__ hn, const float* __restrict__ bias0,
             float* __restrict__ y)
{
    int idx = blockIdx.x * blockDim.x + threadIdx.x;   // over B*OUT
    if (idx >= B_SZ * OUT_SZ) return;
    int b = idx >> 9;
    int o = idx & 511;
    const float* h = hn + (long)b * H_SZ;
    float v = g_xw0[idx] + bias0[o] + h[OUT_SZ * R_SZ + IN_SZ * R_SZ + o];
    float4 w1 = *reinterpret_cast<const float4*>(h + o * R_SZ);
    const float* zb = g_z + b * R_SZ;
    v = fmaf(w1.x, zb[0], v);
    v = fmaf(w1.y, zb[1], v);
    v = fmaf(w1.z, zb[2], v);
    v = fmaf(w1.w, zb[3], v);
    y[idx] = v;
}

// ---------------------------------------------------------------------------
extern "C" void kernel_launch(void* const* d_in, const int* in_sizes, int n_in,
                              void* d_out, int out_size)
{
    const float* x     = (const float*)d_in[0];
    const float* h0    = (const float*)d_in[1];
    const float* c0    = (const float*)d_in[2];
    const float* Wih   = (const float*)d_in[3];
    const float* Whh   = (const float*)d_in[4];
    const float* bih   = (const float*)d_in[5];
    const float* bhh   = (const float*)d_in[6];
    const float* W0    = (const float*)d_in[7];
    const float* bias0 = (const float*)d_in[8];

    float* y     = (float*)d_out;                 // [B, OUT]
    float* h_out = y + B_SZ * OUT_SZ;             // [B, H]
    float* c_out = h_out + B_SZ * H_SZ;           // [B, H]

    dim3 ggrid(NX_SZ / BN, B_SZ / BM);            // (148, 2) = 296 blocks
    gates_gemm_fused<<<ggrid, NTHREADS>>>(x, h0, c0, Wih, Whh, bih, bhh, W0,
                                          h_out, c_out);

    z_kernel<<<B_SZ, 128>>>(h_out, x);

    int m = B_SZ * OUT_SZ;
    y_final<<<(m + 255) / 256, 256>>>(h_out, bias0, y);
}

// round 13
// speedup vs baseline: 1.2222x; 1.2222x over previous
#include <cuda_runtime.h>
#include <cuda_fp16.h>
#include <math.h>
#include <stdint.h>

// Problem constants
#define B_SZ   256
#define IN_SZ  512
#define OUT_SZ 512
#define R_SZ   4
#define H_SZ   4608             // (IN+OUT)*R + OUT
#define G4_SZ  (4*H_SZ)         // 18432  (gate columns)
#define NX_SZ  (G4_SZ + OUT_SZ) // 18944  = 148*128
#define K_TOT  (IN_SZ + H_SZ)   // 5120

// GEMM tile config (fp16 mma.sync m16n8k16)
// One CTA per n-tile: BM = 256 (whole batch) x BN = 128. grid = 148 CTAs.
#define BM 256
#define BN 128
#define BK 32
#define BKP 40                  // padded row (80 B: 16B-aligned, conflict-free)
#define NTHREADS 256            // 8 warps: 4 m-strips x 2 n-strips, 64x64 each
#define A_HALVES (2 * BM * BKP) // both buffers
#define B_HALVES (2 * BN * BKP)
#define SMEM_BYTES ((A_HALVES + B_HALVES) * 2)   // 61440

// Scratch (no cudaMalloc allowed)
__device__ float g_gates[B_SZ * NX_SZ];   // 19.4 MB
__device__ float g_z[B_SZ * R_SZ];

// ---------------------------------------------------------------------------
__device__ __forceinline__ void mma_f16(float c[4],
                                        uint32_t a0, uint32_t a1, uint32_t a2, uint32_t a3,
                                        uint32_t b0, uint32_t b1) {
    asm volatile(
        "mma.sync.aligned.m16n8k16.row.col.f32.f16.f16.f32 "
        "{%0,%1,%2,%3}, {%4,%5,%6,%7}, {%8,%9}, {%0,%1,%2,%3};"
        : "+f"(c[0]), "+f"(c[1]), "+f"(c[2]), "+f"(c[3])
        : "r"(a0), "r"(a1), "r"(a2), "r"(a3), "r"(b0), "r"(b1));
}

__device__ __forceinline__ uint32_t h2u(__half2 h) {
    return *reinterpret_cast<uint32_t*>(&h);
}

__device__ __forceinline__ float sigm(float v) { return 1.0f / (1.0f + expf(-v)); }

// ---------------------------------------------------------------------------
// Kernel 1: C[m, n'] row-major [256 x 18944] into g_gates:
//   n' < G4:  [x|h0] @ [Wih|Whh]^T + (bih+bhh)
//   n' >= G4: x @ W0^T   (K loop only over k<512)
// BM=256 covers the whole batch: each weight tile is fetched/staged ONCE.
// fp16 mma.sync, 8 warps of 64x64, double-buffered dynamic smem.
// ---------------------------------------------------------------------------
__global__ __launch_bounds__(NTHREADS, 1)
void gates_gemm(const float* __restrict__ x,  const float* __restrict__ h0,
                const float* __restrict__ Wih, const float* __restrict__ Whh,
                const float* __restrict__ bih, const float* __restrict__ bhh,
                const float* __restrict__ W0)
{
    extern __shared__ __align__(16) __half dynsmem[];
    // As[buf][row][col] : buf*(BM*BKP) + row*BKP + col
    __half* Asm = dynsmem;
    __half* Bsm = dynsmem + A_HALVES;

    const int tid = threadIdx.x;
    const int bn  = blockIdx.x * BN;
    const bool isW0 = (bn >= G4_SZ);                      // block-uniform
    const int NIT = isW0 ? (IN_SZ / BK) : (K_TOT / BK);   // 16 or 160

    const int warp = tid >> 5;
    const int lane = tid & 31;
    const int wm0 = (warp & 3) * 64;   // 4 m-strips of 64
    const int wn0 = (warp >> 2) * 64;  // 2 n-strips of 64
    const int q   = lane & 3;
    const int t8  = lane >> 2;

    float acc[4][8][4];
#pragma unroll
    for (int mi = 0; mi < 4; mi++)
#pragma unroll
        for (int ni = 0; ni < 8; ni++)
#pragma unroll
            for (int e = 0; e < 4; e++) acc[mi][ni][e] = 0.f;

    // staging: A 256x32 fp32 = 2048 float4 (8/thread); B 128x32 = 1024 (4/thread)
    float4 ra[8], rb[4];

    auto ldg_tile = [&](int t) {
        const int k0 = t * BK;
        const float* baseA; long sA;
        if (k0 < IN_SZ) { baseA = x + k0; sA = IN_SZ; }
        else            { baseA = h0 + (k0 - IN_SZ); sA = H_SZ; }
#pragma unroll
        for (int j = 0; j < 8; j++) {
            int ch = j * 256 + tid, row = ch >> 3, c = ch & 7;
            ra[j] = *reinterpret_cast<const float4*>(baseA + (long)row * sA + c * 4);
        }
        const float* baseB; long sB;
        if (isW0)            { baseB = W0 + (long)(bn - G4_SZ) * IN_SZ + k0; sB = IN_SZ; }
        else if (k0 < IN_SZ) { baseB = Wih + (long)bn * IN_SZ + k0; sB = IN_SZ; }
        else                 { baseB = Whh + (long)bn * H_SZ + (k0 - IN_SZ); sB = H_SZ; }
#pragma unroll
        for (int j = 0; j < 4; j++) {
            int ch = j * 256 + tid, row = ch >> 3, c = ch & 7;
            rb[j] = *reinterpret_cast<const float4*>(baseB + (long)row * sB + c * 4);
        }
    };

    auto sts_tile = [&](int buf) {
        __half* Ab = Asm + buf * (BM * BKP);
        __half* Bb = Bsm + buf * (BN * BKP);
#pragma unroll
        for (int j = 0; j < 8; j++) {
            int ch = j * 256 + tid, row = ch >> 3, c = ch & 7;
            __half2 ha = __floats2half2_rn(ra[j].x, ra[j].y);
            __half2 hb = __floats2half2_rn(ra[j].z, ra[j].w);
            *reinterpret_cast<uint2*>(Ab + row * BKP + c * 4) = make_uint2(h2u(ha), h2u(hb));
        }
#pragma unroll
        for (int j = 0; j < 4; j++) {
            int ch = j * 256 + tid, row = ch >> 3, c = ch & 7;
            __half2 ha = __floats2half2_rn(rb[j].x, rb[j].y);
            __half2 hb = __floats2half2_rn(rb[j].z, rb[j].w);
            *reinterpret_cast<uint2*>(Bb + row * BKP + c * 4) = make_uint2(h2u(ha), h2u(hb));
        }
    };

    auto compute = [&](int buf) {
        const __half* Ab = Asm + buf * (BM * BKP);
        const __half* Bb = Bsm + buf * (BN * BKP);
#pragma unroll
        for (int ks = 0; ks < 2; ks++) {
            const int kb = ks * 16;
            uint32_t a[4][4];
#pragma unroll
            for (int mi = 0; mi < 4; mi++) {
                int r0 = wm0 + mi * 16 + t8;
                a[mi][0] = h2u(*reinterpret_cast<const __half2*>(Ab + r0 * BKP       + kb + 2 * q    ));
                a[mi][1] = h2u(*reinterpret_cast<const __half2*>(Ab + (r0 + 8) * BKP + kb + 2 * q    ));
                a[mi][2] = h2u(*reinterpret_cast<const __half2*>(Ab + r0 * BKP       + kb + 2 * q + 8));
                a[mi][3] = h2u(*reinterpret_cast<const __half2*>(Ab + (r0 + 8) * BKP + kb + 2 * q + 8));
            }
#pragma unroll
            for (int ni = 0; ni < 8; ni++) {
                int nc = wn0 + ni * 8 + t8;
                uint32_t b0 = h2u(*reinterpret_cast<const __half2*>(Bb + nc * BKP + kb + 2 * q    ));
                uint32_t b1 = h2u(*reinterpret_cast<const __half2*>(Bb + nc * BKP + kb + 2 * q + 8));
#pragma unroll
                for (int mi = 0; mi < 4; mi++)
                    mma_f16(acc[mi][ni], a[mi][0], a[mi][1], a[mi][2], a[mi][3], b0, b1);
            }
        }
    };

    // prologue
    ldg_tile(0);
    sts_tile(0);
    __syncthreads();

    int buf = 0;
    for (int t = 1; t < NIT; t++) {
        ldg_tile(t);
        compute(buf);
        sts_tile(buf ^ 1);
        __syncthreads();
        buf ^= 1;
    }
    compute(buf);

    // epilogue: + bias for gate columns, store fp32
#pragma unroll
    for (int ni = 0; ni < 8; ni++) {
        const int n2 = bn + wn0 + ni * 8 + q * 2;
        float bv0 = 0.f, bv1 = 0.f;
        if (!isW0) {
            bv0 = bih[n2] + bhh[n2];
            bv1 = bih[n2 + 1] + bhh[n2 + 1];
        }
#pragma unroll
        for (int mi = 0; mi < 4; mi++) {
            const int row = wm0 + mi * 16 + t8;
            float2 v0 = make_float2(acc[mi][ni][0] + bv0, acc[mi][ni][1] + bv1);
            float2 v1 = make_float2(acc[mi][ni][2] + bv0, acc[mi][ni][3] + bv1);
            *reinterpret_cast<float2*>(g_gates + (long)row * NX_SZ + n2)       = v0;
            *reinterpret_cast<float2*>(g_gates + (long)(row + 8) * NX_SZ + n2) = v1;
        }
    }
}

// ---------------------------------------------------------------------------
// Kernel 2: LSTM elementwise (float4) -> h_new, c_new, PLUS z dots
// (verbatim from the 223.3us round-10 champion)
// ---------------------------------------------------------------------------
__global__ __launch_bounds__(256)
void lstm_eltwise_z(const float* __restrict__ c0, const float* __restrict__ x,
                    float* __restrict__ h_out, float* __restrict__ c_out)
{
    const int idx = blockIdx.x * blockDim.x + threadIdx.x;   // over B*H/4
    if (idx < B_SZ * H_SZ / 4) {
        const int b  = idx / (H_SZ / 4);
        const int h4 = (idx - b * (H_SZ / 4)) * 4;
        const float* gb = g_gates + (long)b * NX_SZ;

        float4 gi4 = *reinterpret_cast<const float4*>(gb + h4);
        float4 gf4 = *reinterpret_cast<const float4*>(gb + H_SZ + h4);
        float4 gg4 = *reinterpret_cast<const float4*>(gb + 2 * H_SZ + h4);
        float4 go4 = *reinterpret_cast<const float4*>(gb + 3 * H_SZ + h4);
        float4 c04 = *reinterpret_cast<const float4*>(c0 + (long)b * H_SZ + h4);

        float4 co, ho;
        float c;
        c = sigm(gf4.x) * c04.x + sigm(gi4.x) * tanhf(gg4.x); co.x = c; ho.x = sigm(go4.x) * tanhf(c);
        c = sigm(gf4.y) * c04.y + sigm(gi4.y) * tanhf(gg4.y); co.y = c; ho.y = sigm(go4.y) * tanhf(c);
        c = sigm(gf4.z) * c04.z + sigm(gi4.z) * tanhf(gg4.z); co.z = c; ho.z = sigm(go4.z) * tanhf(c);
        c = sigm(gf4.w) * c04.w + sigm(gi4.w) * tanhf(gg4.w); co.w = c; ho.w = sigm(go4.w) * tanhf(c);

        *reinterpret_cast<float4*>(c_out + (long)b * H_SZ + h4) = co;
        *reinterpret_cast<float4*>(h_out + (long)b * H_SZ + h4) = ho;
    }

    // z-dots: 1024 (b,r) pairs, one per 64-thread group of the first 256 blocks.
    const int gw = (blockIdx.x * 256 + threadIdx.x) >> 6;   // 64-thread group id
    if (gw < B_SZ * R_SZ) {
        const int lane64 = threadIdx.x & 63;
        const int b = gw >> 2, r = gw & 3;
        const float* gb = g_gates + (long)b * NX_SZ;
        const float* xb = x + b * IN_SZ;
        float s = 0.f;
        for (int i = lane64; i < IN_SZ; i += 64) {
            const int hh = OUT_SZ * R_SZ + r * IN_SZ + i;
            float gi = sigm(gb[hh]);
            float gf = sigm(gb[H_SZ + hh]);
            float gg = tanhf(gb[2 * H_SZ + hh]);
            float go = sigm(gb[3 * H_SZ + hh]);
            float cc = gf * c0[(long)b * H_SZ + hh] + gi * gg;
            float hn = go * tanhf(cc);
            s = fmaf(hn, xb[i], s);
        }
        __shared__ float red[4];
#pragma unroll
        for (int off = 16; off; off >>= 1) s += __shfl_xor_sync(0xffffffffu, s, off);
        const int grp = (threadIdx.x >> 6);
        if ((threadIdx.x & 63) == 0) red[grp] = s;
        __syncthreads();
        if ((threadIdx.x & 31) == 0 && (threadIdx.x & 32)) {
            atomicAdd(&red[grp], s);
        }
        __syncthreads();
        if ((threadIdx.x & 63) == 0) g_z[gw] = red[grp];
    }
}

// ---------------------------------------------------------------------------
// Kernel 3: y[b,o] = xw0[b,o] + bias0[o] + db[b,o] + sum_r dw1[b,o,r]*z[b,r]
// ---------------------------------------------------------------------------
__global__ __launch_bounds__(256)
void y_final(const float* __restrict__ hn, const float* __restrict__ bias0,
             float* __restrict__ y)
{
    int idx = blockIdx.x * blockDim.x + threadIdx.x;   // over B*OUT
    if (idx >= B_SZ * OUT_SZ) return;
    int b = idx >> 9;
    int o = idx & 511;
    const float* h = hn + (long)b * H_SZ;
    float v = g_gates[(long)b * NX_SZ + G4_SZ + o] + bias0[o]
            + h[OUT_SZ * R_SZ + IN_SZ * R_SZ + o];
    float4 w1 = *reinterpret_cast<const float4*>(h + o * R_SZ);
    const float* zb = g_z + b * R_SZ;
    v = fmaf(w1.x, zb[0], v);
    v = fmaf(w1.y, zb[1], v);
    v = fmaf(w1.z, zb[2], v);
    v = fmaf(w1.w, zb[3], v);
    y[idx] = v;
}

// ---------------------------------------------------------------------------
extern "C" void kernel_launch(void* const* d_in, const int* in_sizes, int n_in,
                              void* d_out, int out_size)
{
    const float* x     = (const float*)d_in[0];
    const float* h0    = (const float*)d_in[1];
    const float* c0    = (const float*)d_in[2];
    const float* Wih   = (const float*)d_in[3];
    const float* Whh   = (const float*)d_in[4];
    const float* bih   = (const float*)d_in[5];
    const float* bhh   = (const float*)d_in[6];
    const float* W0    = (const float*)d_in[7];
    const float* bias0 = (const float*)d_in[8];

    float* y     = (float*)d_out;                 // [B, OUT]
    float* h_out = y + B_SZ * OUT_SZ;             // [B, H]
    float* c_out = h_out + B_SZ * H_SZ;           // [B, H]

    cudaFuncSetAttribute(gates_gemm, cudaFuncAttributeMaxDynamicSharedMemorySize, SMEM_BYTES);

    gates_gemm<<<NX_SZ / BN, NTHREADS, SMEM_BYTES>>>(x, h0, Wih, Whh, bih, bhh, W0);

    int n4 = B_SZ * H_SZ / 4;                     // -> 1152 blocks
    lstm_eltwise_z<<<(n4 + 255) / 256, 256>>>(c0, x, h_out, c_out);

    int m = B_SZ * OUT_SZ;
    y_final<<<(m + 255) / 256, 256>>>(h_out, bias0, y);
}

// round 14
// speedup vs baseline: 1.2283x; 1.0049x over previous
#include <cuda_runtime.h>
#include <cuda_fp16.h>
#include <math.h>
#include <stdint.h>

// Problem constants
#define B_SZ   256
#define IN_SZ  512
#define OUT_SZ 512
#define R_SZ   4
#define H_SZ   4608             // (IN+OUT)*R + OUT
#define G4_SZ  (4*H_SZ)         // 18432  (gate columns)
#define NX_SZ  (G4_SZ + OUT_SZ) // 18944  (gates + x@W0^T columns) = 148*128
#define K_TOT  (IN_SZ + H_SZ)   // 5120

// GEMM tile config (fp16 mma.sync m16n8k16) — round-10 measured champion
#define BM 128
#define BN 128
#define BK 32
#define BKP 40                  // padded row (80 B: 16B-aligned, conflict-free)
#define NTHREADS 256

// Scratch (no cudaMalloc allowed)
__device__ float g_gates[B_SZ * NX_SZ];   // 19.4 MB
__device__ float g_z[B_SZ * R_SZ];

// ---------------------------------------------------------------------------
__device__ __forceinline__ void mma_f16(float c[4],
                                        uint32_t a0, uint32_t a1, uint32_t a2, uint32_t a3,
                                        uint32_t b0, uint32_t b1) {
    asm volatile(
        "mma.sync.aligned.m16n8k16.row.col.f32.f16.f16.f32 "
        "{%0,%1,%2,%3}, {%4,%5,%6,%7}, {%8,%9}, {%0,%1,%2,%3};"
        : "+f"(c[0]), "+f"(c[1]), "+f"(c[2]), "+f"(c[3])
        : "r"(a0), "r"(a1), "r"(a2), "r"(a3), "r"(b0), "r"(b1));
}

__device__ __forceinline__ uint32_t h2u(__half2 h) {
    return *reinterpret_cast<uint32_t*>(&h);
}

// Fast transcendentals (MUFU ex2 path). |rel err| ~1e-6, far inside margin.
__device__ __forceinline__ float sigm(float v) {
    return 1.0f / (1.0f + __expf(-v));
}
__device__ __forceinline__ float ftanh(float v) {
    float t = __expf(2.0f * v);
    return (t - 1.0f) / (t + 1.0f);
}

// ---------------------------------------------------------------------------
// Kernel 1: C[m, n'] row-major [256 x 18944] into g_gates:
//   n' < G4:  [x|h0] @ [Wih|Whh]^T + (bih+bhh)
//   n' >= G4: x @ W0^T   (K loop only over k<512)
// fp16 mma.sync, 128x128x32 stages, 8 warps of 32x64, double-buffered smem.
// (byte-identical to the round-10 champion GEMM)
// ---------------------------------------------------------------------------
__global__ __launch_bounds__(NTHREADS, 2)
void gates_gemm(const float* __restrict__ x,  const float* __restrict__ h0,
                const float* __restrict__ Wih, const float* __restrict__ Whh,
                const float* __restrict__ bih, const float* __restrict__ bhh,
                const float* __restrict__ W0)
{
    __shared__ __align__(16) __half As[2][BM][BKP];
    __shared__ __align__(16) __half Bs[2][BN][BKP];

    const int tid = threadIdx.x;
    const int bm  = blockIdx.y * BM;
    const int bn  = blockIdx.x * BN;
    const bool isW0 = (bn >= G4_SZ);                      // block-uniform
    const int NIT = isW0 ? (IN_SZ / BK) : (K_TOT / BK);   // 16 or 160

    const int warp = tid >> 5;
    const int lane = tid & 31;
    const int wm0 = (warp & 3) * 32;   // warp m-strip
    const int wn0 = (warp >> 2) * 64;  // warp n-strip
    const int q   = lane & 3;
    const int t8  = lane >> 2;

    float acc[2][8][4];
#pragma unroll
    for (int mi = 0; mi < 2; mi++)
#pragma unroll
        for (int ni = 0; ni < 8; ni++)
#pragma unroll
            for (int e = 0; e < 4; e++) acc[mi][ni][e] = 0.f;

    float4 ra[4], rb[4];

    auto ldg_tile = [&](int t) {
        const int k0 = t * BK;
        const float* baseA; long sA;
        if (k0 < IN_SZ) { baseA = x + (long)bm * IN_SZ + k0; sA = IN_SZ; }
        else            { baseA = h0 + (long)bm * H_SZ + (k0 - IN_SZ); sA = H_SZ; }
#pragma unroll
        for (int j = 0; j < 4; j++) {
            int ch = j * 256 + tid, row = ch >> 3, c = ch & 7;
            ra[j] = *reinterpret_cast<const float4*>(baseA + (long)row * sA + c * 4);
        }
        const float* baseB; long sB;
        if (isW0)            { baseB = W0 + (long)(bn - G4_SZ) * IN_SZ + k0; sB = IN_SZ; }
        else if (k0 < IN_SZ) { baseB = Wih + (long)bn * IN_SZ + k0; sB = IN_SZ; }
        else                 { baseB = Whh + (long)bn * H_SZ + (k0 - IN_SZ); sB = H_SZ; }
#pragma unroll
        for (int j = 0; j < 4; j++) {
            int ch = j * 256 + tid, row = ch >> 3, c = ch & 7;
            rb[j] = *reinterpret_cast<const float4*>(baseB + (long)row * sB + c * 4);
        }
    };

    auto sts_tile = [&](int buf) {
#pragma unroll
        for (int j = 0; j < 4; j++) {
            int ch = j * 256 + tid, row = ch >> 3, c = ch & 7;
            __half2 ha = __floats2half2_rn(ra[j].x, ra[j].y);
            __half2 hb = __floats2half2_rn(ra[j].z, ra[j].w);
            *reinterpret_cast<uint2*>(&As[buf][row][c * 4]) = make_uint2(h2u(ha), h2u(hb));
        }
#pragma unroll
        for (int j = 0; j < 4; j++) {
            int ch = j * 256 + tid, row = ch >> 3, c = ch & 7;
            __half2 ha = __floats2half2_rn(rb[j].x, rb[j].y);
            __half2 hb = __floats2half2_rn(rb[j].z, rb[j].w);
            *reinterpret_cast<uint2*>(&Bs[buf][row][c * 4]) = make_uint2(h2u(ha), h2u(hb));
        }
    };

    auto compute = [&](int buf) {
#pragma unroll
        for (int ks = 0; ks < 2; ks++) {
            const int kb = ks * 16;
            uint32_t a[2][4];
#pragma unroll
            for (int mi = 0; mi < 2; mi++) {
                int r0 = wm0 + mi * 16 + t8;
                a[mi][0] = h2u(*reinterpret_cast<const __half2*>(&As[buf][r0    ][kb + 2 * q    ]));
                a[mi][1] = h2u(*reinterpret_cast<const __half2*>(&As[buf][r0 + 8][kb + 2 * q    ]));
                a[mi][2] = h2u(*reinterpret_cast<const __half2*>(&As[buf][r0    ][kb + 2 * q + 8]));
                a[mi][3] = h2u(*reinterpret_cast<const __half2*>(&As[buf][r0 + 8][kb + 2 * q + 8]));
            }
#pragma unroll
            for (int ni = 0; ni < 8; ni++) {
                int nc = wn0 + ni * 8 + t8;
                uint32_t b0 = h2u(*reinterpret_cast<const __half2*>(&Bs[buf][nc][kb + 2 * q    ]));
                uint32_t b1 = h2u(*reinterpret_cast<const __half2*>(&Bs[buf][nc][kb + 2 * q + 8]));
                mma_f16(acc[0][ni], a[0][0], a[0][1], a[0][2], a[0][3], b0, b1);
                mma_f16(acc[1][ni], a[1][0], a[1][1], a[1][2], a[1][3], b0, b1);
            }
        }
    };

    // prologue
    ldg_tile(0);
    sts_tile(0);
    __syncthreads();

    int buf = 0;
    for (int t = 1; t < NIT; t++) {
        ldg_tile(t);
        compute(buf);
        sts_tile(buf ^ 1);
        __syncthreads();
        buf ^= 1;
    }
    compute(buf);

    // epilogue: + bias for gate columns, store fp32
#pragma unroll
    for (int ni = 0; ni < 8; ni++) {
        const int n2 = bn + wn0 + ni * 8 + q * 2;
        float bv0 = 0.f, bv1 = 0.f;
        if (!isW0) {
            bv0 = bih[n2] + bhh[n2];
            bv1 = bih[n2 + 1] + bhh[n2 + 1];
        }
#pragma unroll
        for (int mi = 0; mi < 2; mi++) {
            const int row = bm + wm0 + mi * 16 + t8;
            float2 v0 = make_float2(acc[mi][ni][0] + bv0, acc[mi][ni][1] + bv1);
            float2 v1 = make_float2(acc[mi][ni][2] + bv0, acc[mi][ni][3] + bv1);
            *reinterpret_cast<float2*>(g_gates + (long)row * NX_SZ + n2)       = v0;
            *reinterpret_cast<float2*>(g_gates + (long)(row + 8) * NX_SZ + n2) = v1;
        }
    }
}

// ---------------------------------------------------------------------------
// Kernel 2: LSTM elementwise (float4) -> h_new, c_new, PLUS z dots.
// Fast-math transcendentals (MUFU) — ~4x fewer instructions than libdevice.
// ---------------------------------------------------------------------------
__global__ __launch_bounds__(256)
void lstm_eltwise_z(const float* __restrict__ c0, const float* __restrict__ x,
                    float* __restrict__ h_out, float* __restrict__ c_out)
{
    const int idx = blockIdx.x * blockDim.x + threadIdx.x;   // over B*H/4
    if (idx < B_SZ * H_SZ / 4) {
        const int b  = idx / (H_SZ / 4);
        const int h4 = (idx - b * (H_SZ / 4)) * 4;
        const float* gb = g_gates + (long)b * NX_SZ;

        float4 gi4 = *reinterpret_cast<const float4*>(gb + h4);
        float4 gf4 = *reinterpret_cast<const float4*>(gb + H_SZ + h4);
        float4 gg4 = *reinterpret_cast<const float4*>(gb + 2 * H_SZ + h4);
        float4 go4 = *reinterpret_cast<const float4*>(gb + 3 * H_SZ + h4);
        float4 c04 = *reinterpret_cast<const float4*>(c0 + (long)b * H_SZ + h4);

        float4 co, ho;
        float c;
        c = sigm(gf4.x) * c04.x + sigm(gi4.x) * ftanh(gg4.x); co.x = c; ho.x = sigm(go4.x) * ftanh(c);
        c = sigm(gf4.y) * c04.y + sigm(gi4.y) * ftanh(gg4.y); co.y = c; ho.y = sigm(go4.y) * ftanh(c);
        c = sigm(gf4.z) * c04.z + sigm(gi4.z) * ftanh(gg4.z); co.z = c; ho.z = sigm(go4.z) * ftanh(c);
        c = sigm(gf4.w) * c04.w + sigm(gi4.w) * ftanh(gg4.w); co.w = c; ho.w = sigm(go4.w) * ftanh(c);

        *reinterpret_cast<float4*>(c_out + (long)b * H_SZ + h4) = co;
        *reinterpret_cast<float4*>(h_out + (long)b * H_SZ + h4) = ho;
    }

    // z-dots: 1024 (b,r) pairs, one per 64-thread group of the first 256 blocks.
    // Recomputes h_new from gates with the SAME fast-math helpers.
    const int gw = (blockIdx.x * 256 + threadIdx.x) >> 6;   // 64-thread group id
    if (gw < B_SZ * R_SZ) {
        const int lane64 = threadIdx.x & 63;
        const int b = gw >> 2, r = gw & 3;
        const float* gb = g_gates + (long)b * NX_SZ;
        const float* xb = x + b * IN_SZ;
        float s = 0.f;
        for (int i = lane64; i < IN_SZ; i += 64) {
            const int hh = OUT_SZ * R_SZ + r * IN_SZ + i;
            float gi = sigm(gb[hh]);
            float gf = sigm(gb[H_SZ + hh]);
            float gg = ftanh(gb[2 * H_SZ + hh]);
            float go = sigm(gb[3 * H_SZ + hh]);
            float cc = gf * c0[(long)b * H_SZ + hh] + gi * gg;
            float hn = go * ftanh(cc);
            s = fmaf(hn, xb[i], s);
        }
        __shared__ float red[4];
#pragma unroll
        for (int off = 16; off; off >>= 1) s += __shfl_xor_sync(0xffffffffu, s, off);
        const int grp = (threadIdx.x >> 6);
        if ((threadIdx.x & 63) == 0) red[grp] = s;
        __syncthreads();
        if ((threadIdx.x & 31) == 0 && (threadIdx.x & 32)) {
            atomicAdd(&red[grp], s);
        }
        __syncthreads();
        if ((threadIdx.x & 63) == 0) g_z[gw] = red[grp];
    }
}

// ---------------------------------------------------------------------------
// Kernel 3: y[b,o] = xw0[b,o] + bias0[o] + db[b,o] + sum_r dw1[b,o,r]*z[b,r]
// ---------------------------------------------------------------------------
__global__ __launch_bounds__(256)
void y_final(const float* __restrict__ hn, const float* __restrict__ bias0,
             float* __restrict__ y)
{
    int idx = blockIdx.x * blockDim.x + threadIdx.x;   // over B*OUT
    if (idx >= B_SZ * OUT_SZ) return;
    int b = idx >> 9;
    int o = idx & 511;
    const float* h = hn + (long)b * H_SZ;
    float v = g_gates[(long)b * NX_SZ + G4_SZ + o] + bias0[o]
            + h[OUT_SZ * R_SZ + IN_SZ * R_SZ + o];
    float4 w1 = *reinterpret_cast<const float4*>(h + o * R_SZ);
    const float* zb = g_z + b * R_SZ;
    v = fmaf(w1.x, zb[0], v);
    v = fmaf(w1.y, zb[1], v);
    v = fmaf(w1.z, zb[2], v);
    v = fmaf(w1.w, zb[3], v);
    y[idx] = v;
}

// ---------------------------------------------------------------------------
extern "C" void kernel_launch(void* const* d_in, const int* in_sizes, int n_in,
                              void* d_out, int out_size)
{
    const float* x     = (const float*)d_in[0];
    const float* h0    = (const float*)d_in[1];
    const float* c0    = (const float*)d_in[2];
    const float* Wih   = (const float*)d_in[3];
    const float* Whh   = (const float*)d_in[4];
    const float* bih   = (const float*)d_in[5];
    const float* bhh   = (const float*)d_in[6];
    const float* W0    = (const float*)d_in[7];
    const float* bias0 = (const float*)d_in[8];

    float* y     = (float*)d_out;                 // [B, OUT]
    float* h_out = y + B_SZ * OUT_SZ;             // [B, H]
    float* c_out = h_out + B_SZ * H_SZ;           // [B, H]

    dim3 ggrid(NX_SZ / BN, B_SZ / BM);            // (148, 2) = 296 blocks
    gates_gemm<<<ggrid, NTHREADS>>>(x, h0, Wih, Whh, bih, bhh, W0);

    int n4 = B_SZ * H_SZ / 4;                     // -> 1152 blocks
    lstm_eltwise_z<<<(n4 + 255) / 256, 256>>>(c0, x, h_out, c_out);

    int m = B_SZ * OUT_SZ;
    y_final<<<(m + 255) / 256, 256>>>(h_out, bias0, y);
}